// round 4
// baseline (speedup 1.0000x reference)
#include <cuda_runtime.h>
#include <cuda_bf16.h>
#include <math_constants.h>

// ============================================================================
// EuclideanCodebook: nearest-codebook search + gather.
//   x: [N=96000, D=128] fp32, embed: [K=1024, D=128] fp32
//   score_j = 2*x.e_j - ||e_j||^2  (|x|^2 dropped: constant per row under argmax)
//   out = [ quantize (N*128 floats) | embed_ind as float (N floats) ]
// GEMM-shaped compute (12.6G FMAs) done in fp32 via packed fma.rn.f32x2
// (2 FMAs/instr -> ~75 TF/s fp32 ceiling on sm_103a vs 39 TF/s for FFMA-3reg).
// ============================================================================

#define TILE_M   128          // tokens per block
#define CHUNK    64           // codes per pass
#define SROW     132          // padded smem row stride (floats): conflict-free LDS.128
#define NTHREADS 256

__device__ float g_norm[8192];   // ||e_j||^2

// ---------------------------------------------------------------------------
__global__ void norm_kernel(const float* __restrict__ e, int K) {
    int j = blockIdx.x * blockDim.x + threadIdx.x;
    if (j >= K) return;
    const float4* r = (const float4*)(e + (size_t)j * 128);
    float s = 0.f;
#pragma unroll
    for (int v = 0; v < 32; ++v) {
        float4 f = r[v];
        s += f.x * f.x + f.y * f.y + f.z * f.z + f.w * f.w;
    }
    g_norm[j] = s;
}

// ---------------------------------------------------------------------------
// Dynamic smem layout (floats):
//   sx    [128][132]   x tile
//   se    [ 64][132]   code tile
//   snorm [64]
//   sreds [4][128]     per-wc best score
//   sredi [4][128]     per-wc best index (as int)
//   sidx  [128]        final index per token
#define SX_OFF    0
#define SE_OFF    (TILE_M * SROW)                 // 16896
#define SN_OFF    (SE_OFF + CHUNK * SROW)         // +8448 = 25344
#define SRS_OFF   (SN_OFF + 64)                   // 25408
#define SRI_OFF   (SRS_OFF + 512)                 // 25920
#define SIDX_OFF  (SRI_OFF + 512)                 // 26432
#define SMEM_FLOATS (SIDX_OFF + 128)              // 26560
#define SMEM_BYTES  (SMEM_FLOATS * 4)             // 106240

__global__ __launch_bounds__(NTHREADS, 2)
void vq_kernel(const float* __restrict__ x, const float* __restrict__ embed,
               float* __restrict__ out_q, float* __restrict__ out_idx,
               int N, int K) {
    extern __shared__ float smem[];
    float* sx    = smem + SX_OFF;
    float* se    = smem + SE_OFF;
    float* snorm = smem + SN_OFF;
    float* sreds = smem + SRS_OFF;
    int*   sredi = (int*)(smem + SRI_OFF);
    int*   sidx  = (int*)(smem + SIDX_OFF);

    const int tid  = threadIdx.x;
    const int lane = tid & 31;
    const int w    = tid >> 5;        // 0..7
    const int wc   = w & 3;           // code-column group (4)
    const int wt   = w >> 2;          // token-row group (2)
    const int cg   = lane >> 3;       // code sub-group within warp (4)
    const int tg   = lane & 7;        // token sub-group within warp (8)

    const int m0 = blockIdx.x * TILE_M;

    // ---- load x tile: 128 rows x 128 floats, coalesced float4 ----
    for (int v = tid; v < TILE_M * 32; v += NTHREADS) {
        int row = v >> 5, c4 = v & 31;
        int rg  = m0 + row; if (rg >= N) rg = N - 1;
        *(float4*)&sx[row * SROW + c4 * 4] =
            *(const float4*)&x[(size_t)rg * 128 + c4 * 4];
    }

    // per-thread running best over 8 tokens
    float best[8];
    int   bidx[8];
#pragma unroll
    for (int i = 0; i < 8; ++i) { best[i] = -CUDART_INF_F; bidx[i] = 0x7fffffff; }

    const int nchunks = K / CHUNK;
    for (int ci = 0; ci < nchunks; ++ci) {
        __syncthreads();   // protect se reuse (and first-iter sx)
        // ---- load code tile: 64 rows x 128 floats + norms ----
        for (int v = tid; v < CHUNK * 32; v += NTHREADS) {
            int row = v >> 5, c4 = v & 31;
            *(float4*)&se[row * SROW + c4 * 4] =
                *(const float4*)&embed[(size_t)(ci * CHUNK + row) * 128 + c4 * 4];
        }
        if (tid < CHUNK) snorm[tid] = g_norm[ci * CHUNK + tid];
        __syncthreads();

        // ---- 8x4 register tile, packed-f32x2 accumulation over k ----
        unsigned long long acc[8][4];
#pragma unroll
        for (int i = 0; i < 8; ++i)
#pragma unroll
            for (int j = 0; j < 4; ++j) acc[i][j] = 0ull;

#pragma unroll 4
        for (int kk = 0; kk < 128; kk += 4) {
            ulonglong2 e2[4];
#pragma unroll
            for (int j = 0; j < 4; ++j)
                e2[j] = *(const ulonglong2*)&se[(wc * 16 + j * 4 + cg) * SROW + kk];
#pragma unroll
            for (int i = 0; i < 8; ++i) {
                ulonglong2 x2 = *(const ulonglong2*)&sx[(wt * 64 + i * 8 + tg) * SROW + kk];
#pragma unroll
                for (int j = 0; j < 4; ++j) {
                    asm("fma.rn.f32x2 %0, %1, %2, %0;"
                        : "+l"(acc[i][j]) : "l"(x2.x), "l"(e2[j].x));
                    asm("fma.rn.f32x2 %0, %1, %2, %0;"
                        : "+l"(acc[i][j]) : "l"(x2.y), "l"(e2[j].y));
                }
            }
        }

        // ---- chunk epilogue: score + running argmax ----
#pragma unroll
        for (int i = 0; i < 8; ++i) {
#pragma unroll
            for (int j = 0; j < 4; ++j) {
                unsigned long long a = acc[i][j];
                float lo = __uint_as_float((unsigned)(a & 0xffffffffu));
                float hi = __uint_as_float((unsigned)(a >> 32));
                int   cl = wc * 16 + j * 4 + cg;
                float s  = 2.f * (lo + hi) - snorm[cl];
                int   code = ci * CHUNK + cl;
                if (s > best[i]) { best[i] = s; bidx[i] = code; }
            }
        }
    }

    // ---- reduce across cg lanes (lane ^ 8, lane ^ 16) ----
#pragma unroll
    for (int i = 0; i < 8; ++i) {
#pragma unroll
        for (int off = 8; off <= 16; off <<= 1) {
            float os = __shfl_xor_sync(0xffffffffu, best[i], off);
            int   oi = __shfl_xor_sync(0xffffffffu, bidx[i], off);
            if (os > best[i] || (os == best[i] && oi < bidx[i])) {
                best[i] = os; bidx[i] = oi;
            }
        }
    }

    // ---- write per-warp result; combine across 4 wc warps ----
    if (cg == 0) {
#pragma unroll
        for (int i = 0; i < 8; ++i) {
            int t = wt * 64 + i * 8 + tg;
            sreds[wc * 128 + t] = best[i];
            sredi[wc * 128 + t] = bidx[i];
        }
    }
    __syncthreads();

    if (tid < TILE_M) {
        float bs = sreds[tid]; int bi = sredi[tid];
#pragma unroll
        for (int q = 1; q < 4; ++q) {
            float os = sreds[q * 128 + tid]; int oi = sredi[q * 128 + tid];
            if (os > bs || (os == bs && oi < bi)) { bs = os; bi = oi; }
        }
        sidx[tid] = bi;
        if (out_idx != nullptr && m0 + tid < N) out_idx[m0 + tid] = (float)bi;
    }
    __syncthreads();

    // ---- gather: quantize[t] = embed[best[t]] (codebook is L2-resident) ----
    for (int v = tid; v < TILE_M * 32; v += NTHREADS) {
        int row = v >> 5, c4 = v & 31;
        int t = m0 + row;
        if (t < N) {
            float4 val = *(const float4*)&embed[(size_t)sidx[row] * 128 + c4 * 4];
            *(float4*)&out_q[(size_t)t * 128 + c4 * 4] = val;
        }
    }
}

// ---------------------------------------------------------------------------
extern "C" void kernel_launch(void* const* d_in, const int* in_sizes, int n_in,
                              void* d_out, int out_size) {
    const float* x     = (const float*)d_in[0];
    const float* embed = (const float*)d_in[1];
    const int N = in_sizes[0] / 128;
    const int K = in_sizes[1] / 128;

    float* out_q   = (float*)d_out;
    float* out_idx = nullptr;
    if ((long long)out_size >= (long long)N * 128 + N)
        out_idx = out_q + (size_t)N * 128;

    cudaFuncSetAttribute(vq_kernel, cudaFuncAttributeMaxDynamicSharedMemorySize,
                         SMEM_BYTES);

    norm_kernel<<<(K + 127) / 128, 128>>>(embed, K);
    vq_kernel<<<(N + TILE_M - 1) / TILE_M, NTHREADS, SMEM_BYTES>>>(
        x, embed, out_q, out_idx, N, K);
}

// round 7
// speedup vs baseline: 1.1398x; 1.1398x over previous
#include <cuda_runtime.h>
#include <cuda_bf16.h>
#include <math_constants.h>
#include <cstdint>

// ============================================================================
// EuclideanCodebook, bf16 HMMA (mma.sync, baseline PTX: no 'a'-features) +
// exact fp32 rescue for ambiguous tokens.
//   Phase 1: approx scores s = 2*(x_bf16 . e_bf16) - ||e||^2 via
//            mma.sync.m16n8k16 bf16; per-token top-2. Accept top-1 if
//            gap > DELTA (=0.04 ~ 15 sigma of bf16 score-pair error);
//            else push token into g_list (atomic compaction).
//   Phase 2: brute-force exact fp32 (f32x2) argmax for listed tokens only.
// ============================================================================

#define NTHREADS 256
#define TILE_M   128
#define CHUNK_N  64
#define DELTA    0.04f
#define P2_T     16

// smem byte offsets (A/B rows padded to 272B -> conflict-free ldmatrix)
#define SA        272
#define OFF_A     0                       /* 128*272 = 34816 */
#define OFF_B     34816                   /* 2 x 64*272      */
#define BBUF      17408
#define OFF_NRM   69632                   /* 2 x 64 floats   */
#define OFF_M1S   70144                   /* [2][128] float  */
#define OFF_M1I   71168                   /* [2][128] int    */
#define OFF_M2S   72192                   /* [2][128] float  */
#define OFF_SIDX  73216                   /* [128] int       */
#define SMEM_BYTES 73728

__device__ float g_norm[8192];
__device__ int   g_cnt;
__device__ int   g_list[98304];

// ----------------------------------------------------------------- helpers
__device__ __forceinline__ uint32_t smem_u32(const void* p) {
    uint32_t a;
    asm("{ .reg .u64 t; cvta.to.shared.u64 t, %1; cvt.u32.u64 %0, t; }"
        : "=r"(a) : "l"(p));
    return a;
}
__device__ __forceinline__ void ldsm_x4(uint32_t a, uint32_t& r0, uint32_t& r1,
                                        uint32_t& r2, uint32_t& r3) {
    asm volatile("ldmatrix.sync.aligned.m8n8.x4.shared.b16 {%0,%1,%2,%3}, [%4];"
                 : "=r"(r0), "=r"(r1), "=r"(r2), "=r"(r3) : "r"(a));
}
__device__ __forceinline__ void mma16816(float* c, uint32_t a0, uint32_t a1,
                                         uint32_t a2, uint32_t a3,
                                         uint32_t b0, uint32_t b1) {
    asm volatile(
        "mma.sync.aligned.m16n8k16.row.col.f32.bf16.bf16.f32 "
        "{%0,%1,%2,%3}, {%4,%5,%6,%7}, {%8,%9}, {%0,%1,%2,%3};"
        : "+f"(c[0]), "+f"(c[1]), "+f"(c[2]), "+f"(c[3])
        : "r"(a0), "r"(a1), "r"(a2), "r"(a3), "r"(b0), "r"(b1));
}
__device__ __forceinline__ void cvt_store8(char* dst, float4 f) {
    __nv_bfloat162 lo = __floats2bfloat162_rn(f.x, f.y);
    __nv_bfloat162 hi = __floats2bfloat162_rn(f.z, f.w);
    uint2 u;
    u.x = *(uint32_t*)&lo;
    u.y = *(uint32_t*)&hi;
    *(uint2*)dst = u;
}

// ---------------------------------------------------------------------------
__global__ void norm_kernel(const float* __restrict__ e, int K) {
    if (blockIdx.x == 0 && threadIdx.x == 0) g_cnt = 0;
    int j = blockIdx.x * blockDim.x + threadIdx.x;
    if (j >= K) return;
    const float4* r = (const float4*)(e + (size_t)j * 128);
    float s = 0.f;
#pragma unroll
    for (int v = 0; v < 32; ++v) {
        float4 f = r[v];
        s += f.x * f.x + f.y * f.y + f.z * f.z + f.w * f.w;
    }
    g_norm[j] = s;
}

// ---------------------------------------------------------------------------
// Phase 1: bf16 HMMA approx pass. Warp grid: wm = wid>>1 (4 x 32 rows),
// wn = wid&1 (2 x 32 cols of the 64-code chunk).
__global__ __launch_bounds__(NTHREADS, 2)
void vq_hmma_kernel(const float* __restrict__ x, const float* __restrict__ embed,
                    float* __restrict__ out_q, float* __restrict__ out_idx,
                    int N, int K) {
    extern __shared__ __align__(16) char smem[];
    const uint32_t sb = smem_u32(smem);
    const int tid = threadIdx.x, wid = tid >> 5, lane = tid & 31;
    const int wm = wid >> 1, wn = wid & 1;
    const int l15 = lane & 15, lh = lane >> 4;
    const int m0 = blockIdx.x * TILE_M;
    const int nchunks = K / CHUNK_N;

    float* snorm = (float*)(smem + OFF_NRM);
    float* m1s   = (float*)(smem + OFF_M1S);
    int*   m1i   = (int*)(smem + OFF_M1I);
    float* m2s   = (float*)(smem + OFF_M2S);
    int*   sidx  = (int*)(smem + OFF_SIDX);

    // ---- prologue: convert A (x tile) to bf16 smem + B chunk0 + norms ----
    for (int i = tid; i < 4096; i += NTHREADS) {           // 128 x 32 float4
        int row = i >> 5, q = i & 31;
        int rg = m0 + row; if (rg >= N) rg = N - 1;
        float4 f = *(const float4*)&x[(size_t)rg * 128 + q * 4];
        cvt_store8(smem + OFF_A + row * SA + q * 8, f);
    }
    for (int i = tid; i < 2048; i += NTHREADS) {           // 64 x 32 float4
        int row = i >> 5, q = i & 31;
        float4 f = *(const float4*)&embed[(size_t)row * 128 + q * 4];
        cvt_store8(smem + OFF_B + row * SA + q * 8, f);
    }
    if (tid < 64) snorm[tid] = g_norm[tid];

    // per-thread top-2 state for 4 owned rows
    float s1[4], s2[4];
    int   i1[4];
#pragma unroll
    for (int r = 0; r < 4; ++r) { s1[r] = -CUDART_INF_F; s2[r] = -CUDART_INF_F; i1[r] = 0x7fffffff; }

    const uint32_t aAddrBase = sb + OFF_A + (uint32_t)(wm * 32 + l15) * SA + lh * 16;

    for (int c = 0; c < nchunks; ++c) {
        const int buf = c & 1, nbuf = (c + 1) & 1;
        // prefetch-convert B chunk c+1 into the other buffer
        if (c + 1 < nchunks) {
            const float* src = embed + (size_t)(c + 1) * CHUNK_N * 128;
            char* bb = smem + OFF_B + nbuf * BBUF;
            for (int i = tid; i < 2048; i += NTHREADS) {
                int row = i >> 5, q = i & 31;
                float4 f = *(const float4*)&src[(size_t)row * 128 + q * 4];
                cvt_store8(bb + row * SA + q * 8, f);
            }
            if (tid < 64) snorm[nbuf * 64 + tid] = g_norm[(c + 1) * CHUNK_N + tid];
        }
        __syncthreads();

        // ---- MMA: 32x32 warp tile over the 64-code chunk ----
        float acc[2][4][4];
#pragma unroll
        for (int a = 0; a < 2; ++a)
#pragma unroll
            for (int b = 0; b < 4; ++b)
#pragma unroll
                for (int r = 0; r < 4; ++r) acc[a][b][r] = 0.f;

        const uint32_t bAddrBase = sb + OFF_B + buf * BBUF
                                 + (uint32_t)(wn * 32 + l15) * SA + lh * 16;
#pragma unroll
        for (int ks = 0; ks < 8; ++ks) {
            uint32_t a00, a01, a02, a03, a10, a11, a12, a13;
            ldsm_x4(aAddrBase + ks * 32,            a00, a01, a02, a03);
            ldsm_x4(aAddrBase + ks * 32 + 16 * SA,  a10, a11, a12, a13);
            uint32_t p0, p1, p2, p3, q0, q1, q2, q3;
            ldsm_x4(bAddrBase + ks * 32,            p0, p1, p2, p3);   // n-tiles 0,1
            ldsm_x4(bAddrBase + ks * 32 + 16 * SA,  q0, q1, q2, q3);   // n-tiles 2,3
            mma16816(acc[0][0], a00, a01, a02, a03, p0, p2);
            mma16816(acc[0][1], a00, a01, a02, a03, p1, p3);
            mma16816(acc[0][2], a00, a01, a02, a03, q0, q2);
            mma16816(acc[0][3], a00, a01, a02, a03, q1, q3);
            mma16816(acc[1][0], a10, a11, a12, a13, p0, p2);
            mma16816(acc[1][1], a10, a11, a12, a13, p1, p3);
            mma16816(acc[1][2], a10, a11, a12, a13, q0, q2);
            mma16816(acc[1][3], a10, a11, a12, a13, q1, q3);
        }

        // ---- epilogue: score + per-row top-2 (8 distinct cols/thread) ----
        float nrm[8];
        const int cb0 = wn * 32 + (lane & 3) * 2;
#pragma unroll
        for (int b = 0; b < 4; ++b) {
            nrm[b * 2]     = snorm[buf * 64 + cb0 + b * 8];
            nrm[b * 2 + 1] = snorm[buf * 64 + cb0 + b * 8 + 1];
        }
        const int codebase = c * CHUNK_N + cb0;
#pragma unroll
        for (int a = 0; a < 2; ++a)
#pragma unroll
            for (int h = 0; h < 2; ++h) {
                const int slot = a * 2 + h;
#pragma unroll
                for (int b = 0; b < 4; ++b)
#pragma unroll
                    for (int par = 0; par < 2; ++par) {
                        float s = 2.f * acc[a][b][h * 2 + par] - nrm[b * 2 + par];
                        int code = codebase + b * 8 + par;
                        if (s > s1[slot]) {
                            s2[slot] = s1[slot]; s1[slot] = s; i1[slot] = code;
                        } else if (s >= s2[slot]) {
                            s2[slot] = s;
                        }
                    }
            }
        __syncthreads();   // protect buf before next prefetch overwrites it
    }

    // ---- merge top-2 across the 4 lanes of each row quad ----
#pragma unroll
    for (int slot = 0; slot < 4; ++slot) {
#pragma unroll
        for (int off = 1; off <= 2; off <<= 1) {
            float os1 = __shfl_xor_sync(0xffffffffu, s1[slot], off);
            int   oi1 = __shfl_xor_sync(0xffffffffu, i1[slot], off);
            float os2 = __shfl_xor_sync(0xffffffffu, s2[slot], off);
            if (os1 > s1[slot] || (os1 == s1[slot] && oi1 < i1[slot])) {
                s2[slot] = fmaxf(s1[slot], os2);
                s1[slot] = os1; i1[slot] = oi1;
            } else {
                s2[slot] = fmaxf(s2[slot], os1);
            }
        }
    }
    if ((lane & 3) == 0) {
#pragma unroll
        for (int slot = 0; slot < 4; ++slot) {
            int row = wm * 32 + (slot >> 1) * 16 + (slot & 1) * 8 + (lane >> 2);
            m1s[wn * 128 + row] = s1[slot];
            m1i[wn * 128 + row] = i1[slot];
            m2s[wn * 128 + row] = s2[slot];
        }
    }
    __syncthreads();

    // ---- merge the two n-halves; decide exact-vs-approx per token ----
    if (tid < TILE_M) {
        float a1 = m1s[tid],      b1 = m1s[128 + tid];
        int   ai = m1i[tid],      bi = m1i[128 + tid];
        float a2 = m2s[tid],      b2 = m2s[128 + tid];
        float f1, f2; int fi;
        if (b1 > a1 || (b1 == a1 && bi < ai)) {
            f1 = b1; fi = bi; f2 = fmaxf(a1, b2);
        } else {
            f1 = a1; fi = ai; f2 = fmaxf(a2, b1);
        }
        sidx[tid] = fi;
        int t = m0 + tid;
        if (t < N) {
            if (out_idx != nullptr) out_idx[t] = (float)fi;
            if (f1 - f2 <= DELTA) {               // ambiguous -> exact rescue
                int p = atomicAdd(&g_cnt, 1);
                g_list[p] = t;
            }
        }
    }
    __syncthreads();

    // ---- gather quantize rows ----
    for (int i = tid; i < 4096; i += NTHREADS) {
        int row = i >> 5, q = i & 31;
        int t = m0 + row;
        if (t < N) {
            float4 v = *(const float4*)&embed[(size_t)sidx[row] * 128 + q * 4];
            *(float4*)&out_q[(size_t)t * 128 + q * 4] = v;
        }
    }
}

// ---------------------------------------------------------------------------
// Phase 2: exact fp32 argmax for ambiguous tokens (f32x2 SIMT, codebook tiled).
__global__ __launch_bounds__(256, 4)
void rescore_kernel(const float* __restrict__ x, const float* __restrict__ embed,
                    float* __restrict__ out_q, float* __restrict__ out_idx,
                    int N, int K) {
    __shared__ float sx[P2_T][132];
    __shared__ float se[64][132];
    __shared__ float sn2[64];
    __shared__ int   stok[P2_T];

    const int cnt = g_cnt;
    const int base = blockIdx.x * P2_T;
    if (base >= cnt) return;
    const int nt = min(P2_T, cnt - base);
    const int tid = threadIdx.x;

    if (tid < nt) stok[tid] = g_list[base + tid];
    __syncthreads();
    for (int i = tid; i < nt * 32; i += 256) {
        int t = i >> 5, q = i & 31;
        *(float4*)&sx[t][q * 4] = *(const float4*)&x[(size_t)stok[t] * 128 + q * 4];
    }

    const int t_loc = tid >> 4, cs = tid & 15;
    float best = -CUDART_INF_F;
    int   bi   = 0x7fffffff;

    const int nchunks = K / 64;
    for (int c = 0; c < nchunks; ++c) {
        __syncthreads();
        for (int i = tid; i < 2048; i += 256) {
            int row = i >> 5, q = i & 31;
            *(float4*)&se[row][q * 4] =
                *(const float4*)&embed[(size_t)(c * 64 + row) * 128 + q * 4];
        }
        if (tid < 64) sn2[tid] = g_norm[c * 64 + tid];
        __syncthreads();

        if (t_loc < nt) {
#pragma unroll
            for (int j = 0; j < 4; ++j) {
                int cc = cs + j * 16;
                unsigned long long acc0 = 0ull, acc1 = 0ull;
#pragma unroll 8
                for (int kk = 0; kk < 128; kk += 4) {
                    ulonglong2 xv = *(const ulonglong2*)&sx[t_loc][kk];
                    ulonglong2 ev = *(const ulonglong2*)&se[cc][kk];
                    asm("fma.rn.f32x2 %0, %1, %2, %0;" : "+l"(acc0)
                        : "l"(xv.x), "l"(ev.x));
                    asm("fma.rn.f32x2 %0, %1, %2, %0;" : "+l"(acc1)
                        : "l"(xv.y), "l"(ev.y));
                }
                float d = __uint_as_float((unsigned)(acc0 & 0xffffffffu))
                        + __uint_as_float((unsigned)(acc0 >> 32))
                        + __uint_as_float((unsigned)(acc1 & 0xffffffffu))
                        + __uint_as_float((unsigned)(acc1 >> 32));
                float s = 2.f * d - sn2[cc];
                int code = c * 64 + cc;
                if (s > best || (s == best && code < bi)) { best = s; bi = code; }
            }
        }
    }

    // reduce across the 16 lanes of each token group
#pragma unroll
    for (int off = 1; off <= 8; off <<= 1) {
        float os = __shfl_xor_sync(0xffffffffu, best, off);
        int   oi = __shfl_xor_sync(0xffffffffu, bi, off);
        if (os > best || (os == best && oi < bi)) { best = os; bi = oi; }
    }

    if (t_loc < nt) {
        int tok = stok[t_loc];
        if (cs == 0 && out_idx != nullptr) out_idx[tok] = (float)bi;
        const float4* er = (const float4*)&embed[(size_t)bi * 128 + cs * 8];
        float4* oq = (float4*)&out_q[(size_t)tok * 128 + cs * 8];
        oq[0] = er[0];
        oq[1] = er[1];
    }
}

// ---------------------------------------------------------------------------
extern "C" void kernel_launch(void* const* d_in, const int* in_sizes, int n_in,
                              void* d_out, int out_size) {
    const float* x     = (const float*)d_in[0];
    const float* embed = (const float*)d_in[1];
    const int N = in_sizes[0] / 128;
    const int K = in_sizes[1] / 128;

    float* out_q   = (float*)d_out;
    float* out_idx = nullptr;
    if ((long long)out_size >= (long long)N * 128 + N)
        out_idx = out_q + (size_t)N * 128;

    cudaFuncSetAttribute(vq_hmma_kernel, cudaFuncAttributeMaxDynamicSharedMemorySize,
                         SMEM_BYTES);

    norm_kernel<<<(K + 127) / 128, 128>>>(embed, K);
    vq_hmma_kernel<<<(N + TILE_M - 1) / TILE_M, NTHREADS, SMEM_BYTES>>>(
        x, embed, out_q, out_idx, N, K);
    rescore_kernel<<<(N + P2_T - 1) / P2_T, 256>>>(
        x, embed, out_q, out_idx, N, K);
}